// round 7
// baseline (speedup 1.0000x reference)
#include <cuda_runtime.h>
#include <cstdint>

// FastSeqProp: instance-norm(L=200) -> scale/shift -> softmax over C=4
// -> exact JAX threefry categorical (key 42, partitionable) -> straight-through
// -> pad to (N,4,600); outputs [softmax_padded, sampled_padded].
//
// R7: I$ + mem-op diet. Threefry in a rolled loop (small code), pads copied
// by a warp-specialized float4 phase (each pad f4 loaded once, stored twice),
// warp 7 skipped in reductions. All computed values bit-identical to R5/R6
// (rel_err 5.770226e-4 = one tolerated argmax flip).

#define LEN   200
#define LPAD  600
#define NCH   4
#define EPSV  1e-5f
#define TINYF 1.17549435e-38f

__device__ __forceinline__ uint32_t rotl32(uint32_t x, int r) {
    return (x << r) | (x >> (32 - r));
}

__device__ __forceinline__ void tf_round(uint32_t& x0, uint32_t& x1, int r) {
    x0 += x1;
    x1 = rotl32(x1, r);
    x1 ^= x0;
}

__device__ __forceinline__ uint32_t tf_bits_k42(uint32_t idx) {
    // threefry2x32, key=(0,42), counter=(0, idx); out = x0 ^ x1 (partitionable)
    const uint32_t ks0 = 0u;
    const uint32_t ks1 = 42u;
    const uint32_t ks2 = 0x1BD11BDAu ^ ks0 ^ ks1;
    uint32_t x0 = 0u + ks0;
    uint32_t x1 = idx + ks1;

    tf_round(x0, x1, 13); tf_round(x0, x1, 15); tf_round(x0, x1, 26); tf_round(x0, x1, 6);
    x0 += ks1; x1 += ks2 + 1u;
    tf_round(x0, x1, 17); tf_round(x0, x1, 29); tf_round(x0, x1, 16); tf_round(x0, x1, 24);
    x0 += ks2; x1 += ks0 + 2u;
    tf_round(x0, x1, 13); tf_round(x0, x1, 15); tf_round(x0, x1, 26); tf_round(x0, x1, 6);
    x0 += ks0; x1 += ks1 + 3u;
    tf_round(x0, x1, 17); tf_round(x0, x1, 29); tf_round(x0, x1, 16); tf_round(x0, x1, 24);
    x0 += ks1; x1 += ks2 + 4u;
    tf_round(x0, x1, 13); tf_round(x0, x1, 15); tf_round(x0, x1, 26); tf_round(x0, x1, 6);
    x0 += ks2; x1 += ks0 + 5u;

    return x0 ^ x1;
}

// w = -log(u), u = uniform in [tiny,1) from bits; exact logf (matches XLA).
__device__ __forceinline__ float expw_from_bits(uint32_t bits) {
    float f = __uint_as_float((bits >> 9) | 0x3f800000u) - 1.0f;
    float u = fmaxf(f, TINYF);
    return 0.0f - logf(u);
}

__global__ __launch_bounds__(256, 8) void fastseqprop_kernel(
    const float* __restrict__ ts,    // (N,4,200)
    const float* __restrict__ scw,   // (N,4,1)
    const float* __restrict__ shw,   // (N,4,1)
    const float* __restrict__ up,    // (N,4,200)
    const float* __restrict__ dn,    // (N,4,200)
    float* __restrict__ out,         // (2,N,4,600) flattened
    uint32_t half_out)               // N*4*600
{
    const uint32_t n    = blockIdx.x;
    const uint32_t t    = threadIdx.x;
    const uint32_t lane = t & 31u;
    const uint32_t wid  = t >> 5;
    const bool act = (t < LEN);

    __shared__ float red[8][4];
    __shared__ float bcm[4];            // means
    __shared__ float bcr[4];            // rsqrt(var+eps)
    __shared__ float sw[NCH * LEN];     // w = -log(u), layout [c*200 + l]

    const uint32_t base = n * (NCH * LEN);   // == flat gumbel base (N,L,4)

    // ---- phase 1: dense threefry in a rolled loop (small I$ footprint) ----
    // draw j = t + 256k maps to smem slot (t&3)*200 + (t>>2) + 64k
    {
        const uint32_t slot0 = (t & 3u) * LEN + (t >> 2);
        #pragma unroll 1
        for (uint32_t k = 0; k < 3u; k++) {
            const uint32_t b = tf_bits_k42(base + t + k * 256u);
            sw[slot0 + k * 64u] = expw_from_bits(b);
        }
        if (t >= 224u) {
            // j3 = (t-224)+768 = t+544 ; 544&3==0, 544>>2==136
            const uint32_t b3 = tf_bits_k42(base + t + 544u);
            sw[slot0 + 136u] = expw_from_bits(b3);
        }
    }

    // zero warp-7 reduction slots (warp 7 skips the shuffle reductions)
    if (t >= 224u && t < 228u) red[7][t - 224u] = 0.f;

    // ---- phase 2: load ts ----
    float x0 = 0.f, x1 = 0.f, x2 = 0.f, x3 = 0.f;
    if (act) {
        x0 = ts[base + 0 * LEN + t];
        x1 = ts[base + 1 * LEN + t];
        x2 = ts[base + 2 * LEN + t];
        x3 = ts[base + 3 * LEN + t];
    }

    // ---- pass 1: sums -> means (bit-identical tree; /200 hoisted to t0) ----
    if (wid < 7u) {
        float v0 = x0, v1 = x1, v2 = x2, v3 = x3;
        #pragma unroll
        for (int o = 16; o > 0; o >>= 1) {
            v0 += __shfl_down_sync(0xffffffffu, v0, o);
            v1 += __shfl_down_sync(0xffffffffu, v1, o);
            v2 += __shfl_down_sync(0xffffffffu, v2, o);
            v3 += __shfl_down_sync(0xffffffffu, v3, o);
        }
        if (lane == 0) { red[wid][0] = v0; red[wid][1] = v1; red[wid][2] = v2; red[wid][3] = v3; }
    }
    __syncthreads();
    if (t == 0) {
        float s0 = 0.f, s1 = 0.f, s2 = 0.f, s3 = 0.f;
        #pragma unroll
        for (int w = 0; w < 8; w++) { s0 += red[w][0]; s1 += red[w][1]; s2 += red[w][2]; s3 += red[w][3]; }
        bcm[0] = s0 / 200.0f; bcm[1] = s1 / 200.0f;
        bcm[2] = s2 / 200.0f; bcm[3] = s3 / 200.0f;
    }
    __syncthreads();

    const float d0 = act ? (x0 - bcm[0]) : 0.f;
    const float d1 = act ? (x1 - bcm[1]) : 0.f;
    const float d2 = act ? (x2 - bcm[2]) : 0.f;
    const float d3 = act ? (x3 - bcm[3]) : 0.f;

    // ---- pass 2: centered sum of squares -> rsqrt(var+eps) (hoisted) ----
    if (wid < 7u) {
        float v0 = d0 * d0, v1 = d1 * d1, v2 = d2 * d2, v3 = d3 * d3;
        #pragma unroll
        for (int o = 16; o > 0; o >>= 1) {
            v0 += __shfl_down_sync(0xffffffffu, v0, o);
            v1 += __shfl_down_sync(0xffffffffu, v1, o);
            v2 += __shfl_down_sync(0xffffffffu, v2, o);
            v3 += __shfl_down_sync(0xffffffffu, v3, o);
        }
        if (lane == 0) { red[wid][0] = v0; red[wid][1] = v1; red[wid][2] = v2; red[wid][3] = v3; }
    }
    __syncthreads();
    if (t == 0) {
        float s0 = 0.f, s1 = 0.f, s2 = 0.f, s3 = 0.f;
        #pragma unroll
        for (int w = 0; w < 8; w++) { s0 += red[w][0]; s1 += red[w][1]; s2 += red[w][2]; s3 += red[w][3]; }
        bcr[0] = rsqrtf(s0 / 200.0f + EPSV);
        bcr[1] = rsqrtf(s1 / 200.0f + EPSV);
        bcr[2] = rsqrtf(s2 / 200.0f + EPSV);
        bcr[3] = rsqrtf(s3 / 200.0f + EPSV);
    }
    __syncthreads();

    // ---- element phase (t < 200): softmax + race argmin + mid stores ----
    if (act) {
        const uint32_t wbase = n * NCH;
        float sc[4];
        sc[0] = (d0 * bcr[0]) * scw[wbase + 0] + shw[wbase + 0];
        sc[1] = (d1 * bcr[1]) * scw[wbase + 1] + shw[wbase + 1];
        sc[2] = (d2 * bcr[2]) * scw[wbase + 2] + shw[wbase + 2];
        sc[3] = (d3 * bcr[3]) * scw[wbase + 3] + shw[wbase + 3];

        const float mx = fmaxf(fmaxf(sc[0], sc[1]), fmaxf(sc[2], sc[3]));
        float ex[4];
        #pragma unroll
        for (int c = 0; c < 4; c++) ex[c] = expf(sc[c] - mx);
        const float ssum = ((ex[0] + ex[1]) + ex[2]) + ex[3];
        float soft[4];
        #pragma unroll
        for (int c = 0; c < 4; c++) soft[c] = __fdividef(ex[c], ssum);

        // exponential-races argmin: argmin_c w_c / ex_c (cross-multiplied)
        float wb = sw[t];
        float eb = ex[0];
        int   bi = 0;
        #pragma unroll
        for (int c = 1; c < 4; c++) {
            const float wc = sw[(uint32_t)c * LEN + t];
            if (wc * eb < wb * ex[c]) { wb = wc; eb = ex[c]; bi = c; }
        }

        float* out0 = out;
        float* out1 = out + half_out;
        const uint32_t obase = n * (NCH * LPAD);
        #pragma unroll
        for (int c = 0; c < 4; c++) {
            const float s_v = soft[c];
            const float oh  = (c == bi) ? 1.0f : 0.0f;
            const float samp = (oh - s_v) + s_v;   // straight-through
            const uint32_t mid = obase + (uint32_t)c * LPAD + LEN + t;
            out0[mid] = s_v;
            out1[mid] = samp;
        }
    }

    // ---- pad copy phase: warp-specialized float4 copy (pure passthrough) ----
    // wid 0-3: up channel wid ; wid 4-7: dn channel wid-4.
    // Each channel row = 50 float4; loaded once, stored to out0 and out1.
    {
        const uint32_t cw = wid & 3u;
        const float4* src4 = (const float4*)(wid < 4u ? up : dn)
                             + n * 200u + cw * 50u;
        float4* o0 = (float4*)out + n * 600u + cw * 150u + (wid < 4u ? 0u : 100u);
        float4* o1 = o0 + (half_out >> 2);

        const float4 v = src4[lane];
        o0[lane] = v;
        o1[lane] = v;
        if (lane < 18u) {
            const float4 w2 = src4[lane + 32u];
            o0[lane + 32u] = w2;
            o1[lane + 32u] = w2;
        }
    }
}

extern "C" void kernel_launch(void* const* d_in, const int* in_sizes, int n_in,
                              void* d_out, int out_size) {
    const float* ts  = (const float*)d_in[0];
    const float* scw = (const float*)d_in[1];
    const float* shw = (const float*)d_in[2];
    const float* up  = (const float*)d_in[3];
    const float* dn  = (const float*)d_in[4];
    float* out = (float*)d_out;

    const int nseq = in_sizes[0] / (NCH * LEN);          // 8192
    const uint32_t half_out = (uint32_t)(out_size / 2);  // N*4*600

    fastseqprop_kernel<<<nseq, 256>>>(ts, scw, shw, up, dn, out, half_out);
}

// round 8
// speedup vs baseline: 1.0517x; 1.0517x over previous
#include <cuda_runtime.h>
#include <cstdint>

// FastSeqProp: instance-norm(L=200) -> scale/shift -> softmax over C=4
// -> exact JAX threefry categorical (key 42, partitionable) -> straight-through
// -> pad to (N,4,600); outputs [softmax_padded, sampled_padded].
//
// R8 = merge of measured-best pieces, all bit-identical to the validated
// 1-flip kernel (rel_err 5.770226e-4):
//  - R5 preload ordering (ts+weights loaded before the threefry stretch)
//  - fully unrolled threefry (3 interleaved blocks + warp-7 4th)
//  - warp 7 skipped in reductions; the +0.0 partial dropped
//  - cross-warp final sums parallelized over threads 0-3 (channel each)
//  - warp-specialized float4 pad copy

#define LEN   200
#define LPAD  600
#define NCH   4
#define EPSV  1e-5f
#define TINYF 1.17549435e-38f

__device__ __forceinline__ uint32_t rotl32(uint32_t x, int r) {
    return (x << r) | (x >> (32 - r));
}

__device__ __forceinline__ void tf_round(uint32_t& x0, uint32_t& x1, int r) {
    x0 += x1;
    x1 = rotl32(x1, r);
    x1 ^= x0;
}

__device__ __forceinline__ uint32_t tf_bits_k42(uint32_t idx) {
    // threefry2x32, key=(0,42), counter=(0, idx); out = x0 ^ x1 (partitionable)
    const uint32_t ks0 = 0u;
    const uint32_t ks1 = 42u;
    const uint32_t ks2 = 0x1BD11BDAu ^ ks0 ^ ks1;
    uint32_t x0 = 0u + ks0;
    uint32_t x1 = idx + ks1;

    tf_round(x0, x1, 13); tf_round(x0, x1, 15); tf_round(x0, x1, 26); tf_round(x0, x1, 6);
    x0 += ks1; x1 += ks2 + 1u;
    tf_round(x0, x1, 17); tf_round(x0, x1, 29); tf_round(x0, x1, 16); tf_round(x0, x1, 24);
    x0 += ks2; x1 += ks0 + 2u;
    tf_round(x0, x1, 13); tf_round(x0, x1, 15); tf_round(x0, x1, 26); tf_round(x0, x1, 6);
    x0 += ks0; x1 += ks1 + 3u;
    tf_round(x0, x1, 17); tf_round(x0, x1, 29); tf_round(x0, x1, 16); tf_round(x0, x1, 24);
    x0 += ks1; x1 += ks2 + 4u;
    tf_round(x0, x1, 13); tf_round(x0, x1, 15); tf_round(x0, x1, 26); tf_round(x0, x1, 6);
    x0 += ks2; x1 += ks0 + 5u;

    return x0 ^ x1;
}

// w = -log(u), u = uniform in [tiny,1) from bits; exact logf (matches XLA).
__device__ __forceinline__ float expw_from_bits(uint32_t bits) {
    float f = __uint_as_float((bits >> 9) | 0x3f800000u) - 1.0f;
    float u = fmaxf(f, TINYF);
    return 0.0f - logf(u);
}

__global__ __launch_bounds__(256) void fastseqprop_kernel(
    const float* __restrict__ ts,    // (N,4,200)
    const float* __restrict__ scw,   // (N,4,1)
    const float* __restrict__ shw,   // (N,4,1)
    const float* __restrict__ up,    // (N,4,200)
    const float* __restrict__ dn,    // (N,4,200)
    float* __restrict__ out,         // (2,N,4,600) flattened
    uint32_t half_out)               // N*4*600
{
    const uint32_t n    = blockIdx.x;
    const uint32_t t    = threadIdx.x;
    const uint32_t lane = t & 31u;
    const uint32_t wid  = t >> 5;
    const bool act = (t < LEN);

    __shared__ float red[7][4];
    __shared__ float bcm[4];            // means
    __shared__ float bcr[4];            // rsqrt(var+eps)
    __shared__ float sw[NCH * LEN];     // w = -log(u), layout [c*200 + l]

    const uint32_t base = n * (NCH * LEN);   // == flat gumbel base (N,L,4)
    const uint32_t wbase = n * NCH;

    // ---- preload ts + weights (latency hidden under threefry) ----
    float x0 = 0.f, x1 = 0.f, x2 = 0.f, x3 = 0.f;
    float scv[4], shv[4];
    if (act) {
        x0 = ts[base + 0 * LEN + t];
        x1 = ts[base + 1 * LEN + t];
        x2 = ts[base + 2 * LEN + t];
        x3 = ts[base + 3 * LEN + t];
        #pragma unroll
        for (int c = 0; c < 4; c++) {
            scv[c] = scw[wbase + (uint32_t)c];
            shv[c] = shw[wbase + (uint32_t)c];
        }
    }

    // ---- dense threefry: 800 draws; 3 per thread (interleaved), warp-7 4th ----
    {
        const uint32_t j0 = t;
        const uint32_t j1 = t + 256u;
        const uint32_t j2 = t + 512u;
        const uint32_t b0 = tf_bits_k42(base + j0);
        const uint32_t b1 = tf_bits_k42(base + j1);
        const uint32_t b2 = tf_bits_k42(base + j2);
        sw[(j0 & 3u) * LEN + (j0 >> 2)] = expw_from_bits(b0);
        sw[(j1 & 3u) * LEN + (j1 >> 2)] = expw_from_bits(b1);
        sw[(j2 & 3u) * LEN + (j2 >> 2)] = expw_from_bits(b2);
        if (t >= 224u) {
            const uint32_t j3 = (t - 224u) + 768u;
            const uint32_t b3 = tf_bits_k42(base + j3);
            sw[(j3 & 3u) * LEN + (j3 >> 2)] = expw_from_bits(b3);
        }
    }

    // ---- pass 1: sums -> means ----
    if (wid < 7u) {
        float v0 = x0, v1 = x1, v2 = x2, v3 = x3;
        #pragma unroll
        for (int o = 16; o > 0; o >>= 1) {
            v0 += __shfl_down_sync(0xffffffffu, v0, o);
            v1 += __shfl_down_sync(0xffffffffu, v1, o);
            v2 += __shfl_down_sync(0xffffffffu, v2, o);
            v3 += __shfl_down_sync(0xffffffffu, v3, o);
        }
        if (lane == 0) { red[wid][0] = v0; red[wid][1] = v1; red[wid][2] = v2; red[wid][3] = v3; }
    }
    __syncthreads();
    if (t < 4u) {
        // channel t; same add order as validated kernels (w ascending; +0.0 tail dropped)
        float s = red[0][t];
        #pragma unroll
        for (int w = 1; w < 7; w++) s += red[w][t];
        bcm[t] = s / 200.0f;
    }
    __syncthreads();

    const float d0 = act ? (x0 - bcm[0]) : 0.f;
    const float d1 = act ? (x1 - bcm[1]) : 0.f;
    const float d2 = act ? (x2 - bcm[2]) : 0.f;
    const float d3 = act ? (x3 - bcm[3]) : 0.f;

    // ---- pass 2: centered sum of squares -> rsqrt(var+eps) ----
    if (wid < 7u) {
        float v0 = d0 * d0, v1 = d1 * d1, v2 = d2 * d2, v3 = d3 * d3;
        #pragma unroll
        for (int o = 16; o > 0; o >>= 1) {
            v0 += __shfl_down_sync(0xffffffffu, v0, o);
            v1 += __shfl_down_sync(0xffffffffu, v1, o);
            v2 += __shfl_down_sync(0xffffffffu, v2, o);
            v3 += __shfl_down_sync(0xffffffffu, v3, o);
        }
        if (lane == 0) { red[wid][0] = v0; red[wid][1] = v1; red[wid][2] = v2; red[wid][3] = v3; }
    }
    __syncthreads();
    if (t < 4u) {
        float s = red[0][t];
        #pragma unroll
        for (int w = 1; w < 7; w++) s += red[w][t];
        bcr[t] = rsqrtf(s / 200.0f + EPSV);
    }
    __syncthreads();

    // ---- element phase (t < 200): softmax + race argmin + mid stores ----
    if (act) {
        float sc[4];
        sc[0] = (d0 * bcr[0]) * scv[0] + shv[0];
        sc[1] = (d1 * bcr[1]) * scv[1] + shv[1];
        sc[2] = (d2 * bcr[2]) * scv[2] + shv[2];
        sc[3] = (d3 * bcr[3]) * scv[3] + shv[3];

        const float mx = fmaxf(fmaxf(sc[0], sc[1]), fmaxf(sc[2], sc[3]));
        float ex[4];
        #pragma unroll
        for (int c = 0; c < 4; c++) ex[c] = expf(sc[c] - mx);
        const float ssum = ((ex[0] + ex[1]) + ex[2]) + ex[3];
        float soft[4];
        #pragma unroll
        for (int c = 0; c < 4; c++) soft[c] = __fdividef(ex[c], ssum);

        // exponential-races argmin: argmin_c w_c / ex_c (cross-multiplied)
        float wb = sw[t];
        float eb = ex[0];
        int   bi = 0;
        #pragma unroll
        for (int c = 1; c < 4; c++) {
            const float wc = sw[(uint32_t)c * LEN + t];
            if (wc * eb < wb * ex[c]) { wb = wc; eb = ex[c]; bi = c; }
        }

        float* out0 = out;
        float* out1 = out + half_out;
        const uint32_t obase = n * (NCH * LPAD);
        #pragma unroll
        for (int c = 0; c < 4; c++) {
            const float s_v = soft[c];
            const float oh  = (c == bi) ? 1.0f : 0.0f;
            const float samp = (oh - s_v) + s_v;   // straight-through
            const uint32_t mid = obase + (uint32_t)c * LPAD + LEN + t;
            out0[mid] = s_v;
            out1[mid] = samp;
        }
    }

    // ---- pad copy: warp-specialized float4 passthrough ----
    // wid 0-3: up channel wid ; wid 4-7: dn channel wid-4. 50 f4 per row.
    {
        const uint32_t cw = wid & 3u;
        const float4* src4 = (const float4*)(wid < 4u ? up : dn)
                             + n * 200u + cw * 50u;
        float4* o0 = (float4*)out + n * 600u + cw * 150u + (wid < 4u ? 0u : 100u);
        float4* o1 = o0 + (half_out >> 2);

        const float4 v = src4[lane];
        o0[lane] = v;
        o1[lane] = v;
        if (lane < 18u) {
            const float4 w2 = src4[lane + 32u];
            o0[lane + 32u] = w2;
            o1[lane + 32u] = w2;
        }
    }
}

extern "C" void kernel_launch(void* const* d_in, const int* in_sizes, int n_in,
                              void* d_out, int out_size) {
    const float* ts  = (const float*)d_in[0];
    const float* scw = (const float*)d_in[1];
    const float* shw = (const float*)d_in[2];
    const float* up  = (const float*)d_in[3];
    const float* dn  = (const float*)d_in[4];
    float* out = (float*)d_out;

    const int nseq = in_sizes[0] / (NCH * LEN);          // 8192
    const uint32_t half_out = (uint32_t)(out_size / 2);  // N*4*600

    fastseqprop_kernel<<<nseq, 256>>>(ts, scw, shw, up, dn, out, half_out);
}

// round 9
// speedup vs baseline: 1.1246x; 1.0694x over previous
#include <cuda_runtime.h>
#include <cstdint>

// FastSeqProp: instance-norm(L=200) -> scale/shift -> softmax over C=4
// -> exact JAX threefry categorical (key 42, partitionable) -> straight-through
// -> pad to (N,4,600); outputs [softmax_padded, sampled_padded].
//
// R9 = R8 + cp.async prefetch of the up/down pads into smem at kernel start,
// so the tail pad-copy phase reads smem instead of eating raw DRAM latency.
// All float math bit-identical to the validated 1-flip kernel
// (rel_err 5.770226e-4).

#define LEN   200
#define LPAD  600
#define NCH   4
#define EPSV  1e-5f
#define TINYF 1.17549435e-38f

__device__ __forceinline__ uint32_t rotl32(uint32_t x, int r) {
    return (x << r) | (x >> (32 - r));
}

__device__ __forceinline__ void tf_round(uint32_t& x0, uint32_t& x1, int r) {
    x0 += x1;
    x1 = rotl32(x1, r);
    x1 ^= x0;
}

__device__ __forceinline__ uint32_t tf_bits_k42(uint32_t idx) {
    // threefry2x32, key=(0,42), counter=(0, idx); out = x0 ^ x1 (partitionable)
    const uint32_t ks0 = 0u;
    const uint32_t ks1 = 42u;
    const uint32_t ks2 = 0x1BD11BDAu ^ ks0 ^ ks1;
    uint32_t x0 = 0u + ks0;
    uint32_t x1 = idx + ks1;

    tf_round(x0, x1, 13); tf_round(x0, x1, 15); tf_round(x0, x1, 26); tf_round(x0, x1, 6);
    x0 += ks1; x1 += ks2 + 1u;
    tf_round(x0, x1, 17); tf_round(x0, x1, 29); tf_round(x0, x1, 16); tf_round(x0, x1, 24);
    x0 += ks2; x1 += ks0 + 2u;
    tf_round(x0, x1, 13); tf_round(x0, x1, 15); tf_round(x0, x1, 26); tf_round(x0, x1, 6);
    x0 += ks0; x1 += ks1 + 3u;
    tf_round(x0, x1, 17); tf_round(x0, x1, 29); tf_round(x0, x1, 16); tf_round(x0, x1, 24);
    x0 += ks1; x1 += ks2 + 4u;
    tf_round(x0, x1, 13); tf_round(x0, x1, 15); tf_round(x0, x1, 26); tf_round(x0, x1, 6);
    x0 += ks2; x1 += ks0 + 5u;

    return x0 ^ x1;
}

// w = -log(u), u = uniform in [tiny,1) from bits; exact logf (matches XLA).
__device__ __forceinline__ float expw_from_bits(uint32_t bits) {
    float f = __uint_as_float((bits >> 9) | 0x3f800000u) - 1.0f;
    float u = fmaxf(f, TINYF);
    return 0.0f - logf(u);
}

__device__ __forceinline__ void cp_async16(void* smem_dst, const void* gmem_src) {
    uint32_t s = (uint32_t)__cvta_generic_to_shared(smem_dst);
    asm volatile("cp.async.cg.shared.global [%0], [%1], 16;" :: "r"(s), "l"(gmem_src));
}

__global__ __launch_bounds__(256) void fastseqprop_kernel(
    const float* __restrict__ ts,    // (N,4,200)
    const float* __restrict__ scw,   // (N,4,1)
    const float* __restrict__ shw,   // (N,4,1)
    const float* __restrict__ up,    // (N,4,200)
    const float* __restrict__ dn,    // (N,4,200)
    float* __restrict__ out,         // (2,N,4,600) flattened
    uint32_t half_out)               // N*4*600
{
    const uint32_t n    = blockIdx.x;
    const uint32_t t    = threadIdx.x;
    const uint32_t lane = t & 31u;
    const uint32_t wid  = t >> 5;
    const bool act = (t < LEN);

    __shared__ float  red[7][4];
    __shared__ float  bcm[4];            // means
    __shared__ float  bcr[4];            // rsqrt(var+eps)
    __shared__ float  sw[NCH * LEN];     // w = -log(u), layout [c*200 + l]
    __shared__ float4 spad[400];         // [0:200)=up f4, [200:400)=dn f4

    const uint32_t base  = n * (NCH * LEN);   // == flat gumbel base (N,L,4)
    const uint32_t wbase = n * NCH;

    // ---- prefetch pads into smem via cp.async (drains under threefry) ----
    {
        const float4* up4 = (const float4*)up + n * 200u;
        const float4* dn4 = (const float4*)dn + n * 200u;
        // chunk 0: i = t
        if (t < 200u) cp_async16(&spad[t], &up4[t]);
        else          cp_async16(&spad[t], &dn4[t - 200u]);
        // chunk 1: i = t + 256 (only t < 144), always dn region
        if (t < 144u) cp_async16(&spad[t + 256u], &dn4[t + 56u]);
        asm volatile("cp.async.commit_group;");
    }

    // ---- preload ts + weights (latency hidden under threefry) ----
    float x0 = 0.f, x1 = 0.f, x2 = 0.f, x3 = 0.f;
    float scv[4], shv[4];
    if (act) {
        x0 = ts[base + 0 * LEN + t];
        x1 = ts[base + 1 * LEN + t];
        x2 = ts[base + 2 * LEN + t];
        x3 = ts[base + 3 * LEN + t];
        #pragma unroll
        for (int c = 0; c < 4; c++) {
            scv[c] = scw[wbase + (uint32_t)c];
            shv[c] = shw[wbase + (uint32_t)c];
        }
    }

    // ---- dense threefry: 800 draws; 3 per thread (interleaved), warp-7 4th ----
    {
        const uint32_t j0 = t;
        const uint32_t j1 = t + 256u;
        const uint32_t j2 = t + 512u;
        const uint32_t b0 = tf_bits_k42(base + j0);
        const uint32_t b1 = tf_bits_k42(base + j1);
        const uint32_t b2 = tf_bits_k42(base + j2);
        sw[(j0 & 3u) * LEN + (j0 >> 2)] = expw_from_bits(b0);
        sw[(j1 & 3u) * LEN + (j1 >> 2)] = expw_from_bits(b1);
        sw[(j2 & 3u) * LEN + (j2 >> 2)] = expw_from_bits(b2);
        if (t >= 224u) {
            const uint32_t j3 = (t - 224u) + 768u;
            const uint32_t b3 = tf_bits_k42(base + j3);
            sw[(j3 & 3u) * LEN + (j3 >> 2)] = expw_from_bits(b3);
        }
    }

    // ---- pass 1: sums -> means ----
    if (wid < 7u) {
        float v0 = x0, v1 = x1, v2 = x2, v3 = x3;
        #pragma unroll
        for (int o = 16; o > 0; o >>= 1) {
            v0 += __shfl_down_sync(0xffffffffu, v0, o);
            v1 += __shfl_down_sync(0xffffffffu, v1, o);
            v2 += __shfl_down_sync(0xffffffffu, v2, o);
            v3 += __shfl_down_sync(0xffffffffu, v3, o);
        }
        if (lane == 0) { red[wid][0] = v0; red[wid][1] = v1; red[wid][2] = v2; red[wid][3] = v3; }
    }
    __syncthreads();
    if (t < 4u) {
        // channel t; same add order as validated kernels (w ascending)
        float s = red[0][t];
        #pragma unroll
        for (int w = 1; w < 7; w++) s += red[w][t];
        bcm[t] = s / 200.0f;
    }
    __syncthreads();

    const float d0 = act ? (x0 - bcm[0]) : 0.f;
    const float d1 = act ? (x1 - bcm[1]) : 0.f;
    const float d2 = act ? (x2 - bcm[2]) : 0.f;
    const float d3 = act ? (x3 - bcm[3]) : 0.f;

    // ---- pass 2: centered sum of squares -> rsqrt(var+eps) ----
    if (wid < 7u) {
        float v0 = d0 * d0, v1 = d1 * d1, v2 = d2 * d2, v3 = d3 * d3;
        #pragma unroll
        for (int o = 16; o > 0; o >>= 1) {
            v0 += __shfl_down_sync(0xffffffffu, v0, o);
            v1 += __shfl_down_sync(0xffffffffu, v1, o);
            v2 += __shfl_down_sync(0xffffffffu, v2, o);
            v3 += __shfl_down_sync(0xffffffffu, v3, o);
        }
        if (lane == 0) { red[wid][0] = v0; red[wid][1] = v1; red[wid][2] = v2; red[wid][3] = v3; }
    }
    __syncthreads();
    if (t < 4u) {
        float s = red[0][t];
        #pragma unroll
        for (int w = 1; w < 7; w++) s += red[w][t];
        bcr[t] = rsqrtf(s / 200.0f + EPSV);
    }
    __syncthreads();

    // ---- element phase (t < 200): softmax + race argmin + mid stores ----
    if (act) {
        float sc[4];
        sc[0] = (d0 * bcr[0]) * scv[0] + shv[0];
        sc[1] = (d1 * bcr[1]) * scv[1] + shv[1];
        sc[2] = (d2 * bcr[2]) * scv[2] + shv[2];
        sc[3] = (d3 * bcr[3]) * scv[3] + shv[3];

        const float mx = fmaxf(fmaxf(sc[0], sc[1]), fmaxf(sc[2], sc[3]));
        float ex[4];
        #pragma unroll
        for (int c = 0; c < 4; c++) ex[c] = expf(sc[c] - mx);
        const float ssum = ((ex[0] + ex[1]) + ex[2]) + ex[3];
        float soft[4];
        #pragma unroll
        for (int c = 0; c < 4; c++) soft[c] = __fdividef(ex[c], ssum);

        // exponential-races argmin: argmin_c w_c / ex_c (cross-multiplied)
        float wb = sw[t];
        float eb = ex[0];
        int   bi = 0;
        #pragma unroll
        for (int c = 1; c < 4; c++) {
            const float wc = sw[(uint32_t)c * LEN + t];
            if (wc * eb < wb * ex[c]) { wb = wc; eb = ex[c]; bi = c; }
        }

        float* out0 = out;
        float* out1 = out + half_out;
        const uint32_t obase = n * (NCH * LPAD);
        #pragma unroll
        for (int c = 0; c < 4; c++) {
            const float s_v = soft[c];
            const float oh  = (c == bi) ? 1.0f : 0.0f;
            const float samp = (oh - s_v) + s_v;   // straight-through
            const uint32_t mid = obase + (uint32_t)c * LPAD + LEN + t;
            out0[mid] = s_v;
            out1[mid] = samp;
        }
    }

    // ---- pad copy: from prefetched smem, warp-specialized float4 ----
    asm volatile("cp.async.wait_group 0;");
    __syncthreads();
    {
        const uint32_t cw = wid & 3u;
        const uint32_t soff = (wid < 4u ? 0u : 200u) + cw * 50u;
        float4* o0 = (float4*)out + n * 600u + cw * 150u + (wid < 4u ? 0u : 100u);
        float4* o1 = o0 + (half_out >> 2);

        const float4 v = spad[soff + lane];
        o0[lane] = v;
        o1[lane] = v;
        if (lane < 18u) {
            const float4 w2 = spad[soff + 32u + lane];
            o0[lane + 32u] = w2;
            o1[lane + 32u] = w2;
        }
    }
}

extern "C" void kernel_launch(void* const* d_in, const int* in_sizes, int n_in,
                              void* d_out, int out_size) {
    const float* ts  = (const float*)d_in[0];
    const float* scw = (const float*)d_in[1];
    const float* shw = (const float*)d_in[2];
    const float* up  = (const float*)d_in[3];
    const float* dn  = (const float*)d_in[4];
    float* out = (float*)d_out;

    const int nseq = in_sizes[0] / (NCH * LEN);          // 8192
    const uint32_t half_out = (uint32_t)(out_size / 2);  // N*4*600

    fastseqprop_kernel<<<nseq, 256>>>(ts, scw, shw, up, dn, out, half_out);
}

// round 10
// speedup vs baseline: 1.1775x; 1.0471x over previous
#include <cuda_runtime.h>
#include <cstdint>

// FastSeqProp: instance-norm(L=200) -> scale/shift -> softmax over C=4
// -> exact JAX threefry categorical (key 42, partitionable) -> straight-through
// -> pad to (N,4,600); outputs [softmax_padded, sampled_padded].
//
// R10: warp-specialized DMA warp. Warp 7 prefetches all pads (cp.async),
// does its 4 threefry draws, bar.arrive's, then copies pads out alone —
// fully overlapped with warps 0-6's reductions/element phase (named
// barriers, count 224). All float math bit-identical to the validated
// 1-flip kernel (rel_err 5.770226e-4).

#define LEN   200
#define LPAD  600
#define NCH   4
#define EPSV  1e-5f
#define TINYF 1.17549435e-38f

__device__ __forceinline__ uint32_t rotl32(uint32_t x, int r) {
    return (x << r) | (x >> (32 - r));
}

__device__ __forceinline__ void tf_round(uint32_t& x0, uint32_t& x1, int r) {
    x0 += x1;
    x1 = rotl32(x1, r);
    x1 ^= x0;
}

__device__ __forceinline__ uint32_t tf_bits_k42(uint32_t idx) {
    // threefry2x32, key=(0,42), counter=(0, idx); out = x0 ^ x1 (partitionable)
    const uint32_t ks0 = 0u;
    const uint32_t ks1 = 42u;
    const uint32_t ks2 = 0x1BD11BDAu ^ ks0 ^ ks1;
    uint32_t x0 = 0u + ks0;
    uint32_t x1 = idx + ks1;

    tf_round(x0, x1, 13); tf_round(x0, x1, 15); tf_round(x0, x1, 26); tf_round(x0, x1, 6);
    x0 += ks1; x1 += ks2 + 1u;
    tf_round(x0, x1, 17); tf_round(x0, x1, 29); tf_round(x0, x1, 16); tf_round(x0, x1, 24);
    x0 += ks2; x1 += ks0 + 2u;
    tf_round(x0, x1, 13); tf_round(x0, x1, 15); tf_round(x0, x1, 26); tf_round(x0, x1, 6);
    x0 += ks0; x1 += ks1 + 3u;
    tf_round(x0, x1, 17); tf_round(x0, x1, 29); tf_round(x0, x1, 16); tf_round(x0, x1, 24);
    x0 += ks1; x1 += ks2 + 4u;
    tf_round(x0, x1, 13); tf_round(x0, x1, 15); tf_round(x0, x1, 26); tf_round(x0, x1, 6);
    x0 += ks2; x1 += ks0 + 5u;

    return x0 ^ x1;
}

// w = -log(u), u = uniform in [tiny,1) from bits; exact logf (matches XLA).
__device__ __forceinline__ float expw_from_bits(uint32_t bits) {
    float f = __uint_as_float((bits >> 9) | 0x3f800000u) - 1.0f;
    float u = fmaxf(f, TINYF);
    return 0.0f - logf(u);
}

__device__ __forceinline__ void cp_async16(void* smem_dst, const void* gmem_src) {
    uint32_t s = (uint32_t)__cvta_generic_to_shared(smem_dst);
    asm volatile("cp.async.cg.shared.global [%0], [%1], 16;" :: "r"(s), "l"(gmem_src));
}

__global__ __launch_bounds__(256) void fastseqprop_kernel(
    const float* __restrict__ ts,    // (N,4,200)
    const float* __restrict__ scw,   // (N,4,1)
    const float* __restrict__ shw,   // (N,4,1)
    const float* __restrict__ up,    // (N,4,200)
    const float* __restrict__ dn,    // (N,4,200)
    float* __restrict__ out,         // (2,N,4,600) flattened
    uint32_t half_out)               // N*4*600
{
    const uint32_t n    = blockIdx.x;
    const uint32_t t    = threadIdx.x;
    const uint32_t lane = t & 31u;
    const uint32_t wid  = t >> 5;

    __shared__ float  red[7][4];
    __shared__ float  bcm[4];            // means
    __shared__ float  bcr[4];            // rsqrt(var+eps)
    __shared__ float  sw[NCH * LEN];     // w = -log(u), layout [c*200 + l]
    __shared__ float4 spad[400];         // [0:200)=up f4, [200:400)=dn f4

    const uint32_t base = n * (NCH * LEN);   // == flat gumbel base (N,L,4)

    // ================= warp 7: DMA warp + 4th threefry draw =================
    if (wid == 7u) {
        const float4* up4 = (const float4*)up + n * 200u;
        const float4* dn4 = (const float4*)dn + n * 200u;
        // each lane fetches slots {i*32+lane} -> reads back only its own data
        #pragma unroll
        for (uint32_t i = 0; i < 13u; i++) {
            const uint32_t idx = i * 32u + lane;
            if (idx < 400u) {
                const float4* src = (idx < 200u) ? (up4 + idx) : (dn4 + (idx - 200u));
                cp_async16(&spad[idx], src);
            }
        }
        asm volatile("cp.async.commit_group;" ::: "memory");

        // 4 threefry draws: j = t, t+256, t+512, t+544
        {
            const uint32_t j0 = t;
            const uint32_t j1 = t + 256u;
            const uint32_t j2 = t + 512u;
            const uint32_t j3 = t + 544u;
            const uint32_t b0 = tf_bits_k42(base + j0);
            const uint32_t b1 = tf_bits_k42(base + j1);
            const uint32_t b2 = tf_bits_k42(base + j2);
            const uint32_t b3 = tf_bits_k42(base + j3);
            sw[(j0 & 3u) * LEN + (j0 >> 2)] = expw_from_bits(b0);
            sw[(j1 & 3u) * LEN + (j1 >> 2)] = expw_from_bits(b1);
            sw[(j2 & 3u) * LEN + (j2 >> 2)] = expw_from_bits(b2);
            sw[(j3 & 3u) * LEN + (j3 >> 2)] = expw_from_bits(b3);
        }
        // publish sw writes to warps 0-6 (they bar.sync 1 before argmin)
        asm volatile("bar.arrive 1, 256;" ::: "memory");

        // drain pad prefetch; lanes read only their own cp.async'd slots
        asm volatile("cp.async.wait_group 0;" ::: "memory");

        float4* o0 = (float4*)out + n * 600u;
        float4* o1 = o0 + (half_out >> 2);
        #pragma unroll 1
        for (uint32_t i = 0; i < 13u; i++) {
            const uint32_t idx = i * 32u + lane;
            if (idx < 400u) {
                const float4 v = spad[idx];
                uint32_t off;
                if (idx < 200u) {
                    const uint32_t ch = idx / 50u;
                    off = ch * 150u + (idx - ch * 50u);
                } else {
                    const uint32_t j  = idx - 200u;
                    const uint32_t ch = j / 50u;
                    off = ch * 150u + 100u + (j - ch * 50u);
                }
                o0[off] = v;
                o1[off] = v;
            }
        }
        return;
    }

    // ================= warps 0-6: norm + softmax + sample =================
    const bool act = (t < LEN);
    const uint32_t wbase = n * NCH;

    // preload ts + weights (latency hidden under threefry)
    float x0 = 0.f, x1 = 0.f, x2 = 0.f, x3 = 0.f;
    float scv[4], shv[4];
    if (act) {
        x0 = ts[base + 0 * LEN + t];
        x1 = ts[base + 1 * LEN + t];
        x2 = ts[base + 2 * LEN + t];
        x3 = ts[base + 3 * LEN + t];
        #pragma unroll
        for (int c = 0; c < 4; c++) {
            scv[c] = scw[wbase + (uint32_t)c];
            shv[c] = shw[wbase + (uint32_t)c];
        }
    }

    // dense threefry: 3 draws per thread (j = t, t+256, t+512)
    {
        const uint32_t j0 = t;
        const uint32_t j1 = t + 256u;
        const uint32_t j2 = t + 512u;
        const uint32_t b0 = tf_bits_k42(base + j0);
        const uint32_t b1 = tf_bits_k42(base + j1);
        const uint32_t b2 = tf_bits_k42(base + j2);
        sw[(j0 & 3u) * LEN + (j0 >> 2)] = expw_from_bits(b0);
        sw[(j1 & 3u) * LEN + (j1 >> 2)] = expw_from_bits(b1);
        sw[(j2 & 3u) * LEN + (j2 >> 2)] = expw_from_bits(b2);
    }

    // ---- pass 1: sums -> means ----
    {
        float v0 = x0, v1 = x1, v2 = x2, v3 = x3;
        #pragma unroll
        for (int o = 16; o > 0; o >>= 1) {
            v0 += __shfl_down_sync(0xffffffffu, v0, o);
            v1 += __shfl_down_sync(0xffffffffu, v1, o);
            v2 += __shfl_down_sync(0xffffffffu, v2, o);
            v3 += __shfl_down_sync(0xffffffffu, v3, o);
        }
        if (lane == 0) { red[wid][0] = v0; red[wid][1] = v1; red[wid][2] = v2; red[wid][3] = v3; }
    }
    asm volatile("bar.sync 2, 224;" ::: "memory");
    if (t < 4u) {
        float s = red[0][t];
        #pragma unroll
        for (int w = 1; w < 7; w++) s += red[w][t];
        bcm[t] = s / 200.0f;
    }
    asm volatile("bar.sync 2, 224;" ::: "memory");

    const float d0 = act ? (x0 - bcm[0]) : 0.f;
    const float d1 = act ? (x1 - bcm[1]) : 0.f;
    const float d2 = act ? (x2 - bcm[2]) : 0.f;
    const float d3 = act ? (x3 - bcm[3]) : 0.f;

    // ---- pass 2: centered sum of squares -> rsqrt(var+eps) ----
    {
        float v0 = d0 * d0, v1 = d1 * d1, v2 = d2 * d2, v3 = d3 * d3;
        #pragma unroll
        for (int o = 16; o > 0; o >>= 1) {
            v0 += __shfl_down_sync(0xffffffffu, v0, o);
            v1 += __shfl_down_sync(0xffffffffu, v1, o);
            v2 += __shfl_down_sync(0xffffffffu, v2, o);
            v3 += __shfl_down_sync(0xffffffffu, v3, o);
        }
        if (lane == 0) { red[wid][0] = v0; red[wid][1] = v1; red[wid][2] = v2; red[wid][3] = v3; }
    }
    // pairs with warp 7's bar.arrive: orders red writes AND warp7's sw writes
    asm volatile("bar.sync 1, 256;" ::: "memory");
    if (t < 4u) {
        float s = red[0][t];
        #pragma unroll
        for (int w = 1; w < 7; w++) s += red[w][t];
        bcr[t] = rsqrtf(s / 200.0f + EPSV);
    }
    asm volatile("bar.sync 2, 224;" ::: "memory");

    // ---- element phase (t < 200): softmax + race argmin + mid stores ----
    if (act) {
        float sc[4];
        sc[0] = (d0 * bcr[0]) * scv[0] + shv[0];
        sc[1] = (d1 * bcr[1]) * scv[1] + shv[1];
        sc[2] = (d2 * bcr[2]) * scv[2] + shv[2];
        sc[3] = (d3 * bcr[3]) * scv[3] + shv[3];

        const float mx = fmaxf(fmaxf(sc[0], sc[1]), fmaxf(sc[2], sc[3]));
        float ex[4];
        #pragma unroll
        for (int c = 0; c < 4; c++) ex[c] = expf(sc[c] - mx);
        const float ssum = ((ex[0] + ex[1]) + ex[2]) + ex[3];
        float soft[4];
        #pragma unroll
        for (int c = 0; c < 4; c++) soft[c] = __fdividef(ex[c], ssum);

        // exponential-races argmin: argmin_c w_c / ex_c (cross-multiplied)
        float wb = sw[t];
        float eb = ex[0];
        int   bi = 0;
        #pragma unroll
        for (int c = 1; c < 4; c++) {
            const float wc = sw[(uint32_t)c * LEN + t];
            if (wc * eb < wb * ex[c]) { wb = wc; eb = ex[c]; bi = c; }
        }

        float* out0 = out;
        float* out1 = out + half_out;
        const uint32_t obase = n * (NCH * LPAD);
        #pragma unroll
        for (int c = 0; c < 4; c++) {
            const float s_v = soft[c];
            const float oh  = (c == bi) ? 1.0f : 0.0f;
            const float samp = (oh - s_v) + s_v;   // straight-through
            const uint32_t mid = obase + (uint32_t)c * LPAD + LEN + t;
            out0[mid] = s_v;
            out1[mid] = samp;
        }
    }
}

extern "C" void kernel_launch(void* const* d_in, const int* in_sizes, int n_in,
                              void* d_out, int out_size) {
    const float* ts  = (const float*)d_in[0];
    const float* scw = (const float*)d_in[1];
    const float* shw = (const float*)d_in[2];
    const float* up  = (const float*)d_in[3];
    const float* dn  = (const float*)d_in[4];
    float* out = (float*)d_out;

    const int nseq = in_sizes[0] / (NCH * LEN);          // 8192
    const uint32_t half_out = (uint32_t)(out_size / 2);  // N*4*600

    fastseqprop_kernel<<<nseq, 256>>>(ts, scw, shw, up, dn, out, half_out);
}